// round 13
// baseline (speedup 1.0000x reference)
#include <cuda_runtime.h>
#include <cuda_bf16.h>
#include <cstdint>

// Problem dims (fixed)
#define HID   1024
#define NBAT  16
#define SEQ   1024
#define MTOT  (NBAT * SEQ)        // 16384

// ============================================================================
// PTX helpers (base sm_103 target)
// ============================================================================
__device__ __forceinline__ uint32_t smem_u32_of(const void* p) {
    uint32_t a;
    asm("{ .reg .u64 t; cvta.to.shared.u64 t, %1; cvt.u32.u64 %0, t; }"
        : "=r"(a) : "l"(p));
    return a;
}

__device__ __forceinline__ void cp16(uint32_t s, const void* g) {
    asm volatile("cp.async.cg.shared.global [%0], [%1], 16;" :: "r"(s), "l"(g));
}
#define CP_COMMIT() asm volatile("cp.async.commit_group;" ::: "memory")
#define CP_WAIT(N)  asm volatile("cp.async.wait_group %0;" :: "n"(N) : "memory")

__device__ __forceinline__ void ldsm4(uint32_t* r, uint32_t addr) {
    asm volatile("ldmatrix.sync.aligned.m8n8.x4.shared.b16 {%0,%1,%2,%3}, [%4];"
        : "=r"(r[0]), "=r"(r[1]), "=r"(r[2]), "=r"(r[3]) : "r"(addr));
}

__device__ __forceinline__ void sts16(uint32_t addr, uint32_t a, uint32_t b,
                                      uint32_t c, uint32_t d) {
    asm volatile("st.shared.v4.b32 [%0], {%1,%2,%3,%4};"
        :: "r"(addr), "r"(a), "r"(b), "r"(c), "r"(d) : "memory");
}

__device__ __forceinline__ void mma_bf16(float* c, const uint32_t* a, const uint32_t* b) {
    asm volatile(
        "mma.sync.aligned.m16n8k16.row.col.f32.bf16.bf16.f32 "
        "{%0,%1,%2,%3}, {%4,%5,%6,%7}, {%8,%9}, {%0,%1,%2,%3};"
        : "+f"(c[0]), "+f"(c[1]), "+f"(c[2]), "+f"(c[3])
        : "r"(a[0]), "r"(a[1]), "r"(a[2]), "r"(a[3]), "r"(b[0]), "r"(b[1]));
}

// Conflict-free swizzle for 64-byte smem rows (validated R8)
__device__ __forceinline__ uint32_t sw64(uint32_t o) { return o ^ ((o >> 3) & 0x30); }

__device__ __forceinline__ uint32_t pack_hi(float x, float y) {
    __nv_bfloat162 t = __halves2bfloat162(__float2bfloat16(x), __float2bfloat16(y));
    return *reinterpret_cast<uint32_t*>(&t);
}
__device__ __forceinline__ uint32_t pack_lo(float x, float y) {
    __nv_bfloat16 hx = __float2bfloat16(x);
    __nv_bfloat16 hy = __float2bfloat16(y);
    __nv_bfloat162 t = __halves2bfloat162(
        __float2bfloat16(x - __bfloat162float(hx)),
        __float2bfloat16(y - __bfloat162float(hy)));
    return *reinterpret_cast<uint32_t*>(&t);
}

// ============================================================================
// Device global scratch
// ============================================================================
__device__ __align__(16) __nv_bfloat16 g_Qh[MTOT * HID],  g_Ql[MTOT * HID];
__device__ __align__(16) __nv_bfloat16 g_Kh[MTOT * HID],  g_Kl[MTOT * HID];
__device__ __align__(16) __nv_bfloat16 g_VTh[MTOT * HID], g_VTl[MTOT * HID]; // ld=16384
__device__ __align__(16) float         g_S [MTOT * SEQ];
__device__ __align__(16) __nv_bfloat16 g_Ph[MTOT * SEQ],  g_Pl[MTOT * SEQ];

// ============================================================================
// Common tiling
// ============================================================================
#define KDEPTH   1024
#define BKC      32
#define NCHUNK   (KDEPTH / BKC)     // 32
#define ROWB     64                 // bytes per smem row
#define TILE_B   8192               // 128 rows x 64 B
#define STAGE_B  (4 * TILE_B)       // Ah, Al, Bh, Bl = 32 KB
#define NSTAGE   3
#define GEMM_SMEM  (1024 + NSTAGE * STAGE_B)   // cp.async kernel (~97 KB, occ 2)
#define CONV_SMEM  (1024 + 2 * STAGE_B)        // conv kernel (2 stages, ~65 KB)

// ============================================================================
// gemm_conv: NT GEMM with FUSED fp32 -> (bf16 hi, lo) conversion of BOTH
// operands in the loader. For the three projection GEMMs.
//   D[m][n] = sum_k A[m][k]*B[n][k]  (hi*hi + hi*lo + lo*hi, fp32 accum)
//   Output: bf16 pair (Ch, Cl) + bias.  BIAS_MODE: 1 per-col, 2 per-row.
// ============================================================================
template<int BIAS_MODE>
__global__ void __launch_bounds__(256, 1)
gemm_conv(const float* __restrict__ Af, int lda,
          const float* __restrict__ Bf, int ldb,
          const float* __restrict__ bias,
          __nv_bfloat16* __restrict__ Ch, __nv_bfloat16* __restrict__ Cl,
          int ldc)
{
    extern __shared__ char smem[];
    const int tid  = threadIdx.x;
    const int wid  = tid >> 5;
    const int lane = tid & 31;
    const int wm   = wid >> 2;
    const int wn   = wid & 3;

    const int rowBase = blockIdx.y * 128;
    const int colBase = blockIdx.x * 128;

    const uint32_t raw  = smem_u32_of(smem);
    const uint32_t base = (raw + 1023u) & ~1023u;

    const float* cAf = Af + (size_t)rowBase * lda;
    const float* cBf = Bf + (size_t)colBase * ldb;

    // Pipeline registers: 2 slots x 2 float4 per operand
    float4 ra[2][2], rb[2][2];

    auto ldg_chunk = [&](int k0) {
#pragma unroll
        for (int it = 0; it < 2; ++it) {
            const int slot = tid + it * 256;   // 0..511
            const int r    = slot >> 2;        // 0..127
            const int g    = slot & 3;         // 8-float group
            const float* pa = cAf + (size_t)r * lda + k0 + g * 8;
            const float* pb = cBf + (size_t)r * ldb + k0 + g * 8;
            ra[it][0] = __ldg(reinterpret_cast<const float4*>(pa));
            ra[it][1] = __ldg(reinterpret_cast<const float4*>(pa + 4));
            rb[it][0] = __ldg(reinterpret_cast<const float4*>(pb));
            rb[it][1] = __ldg(reinterpret_cast<const float4*>(pb + 4));
        }
    };

    auto sts_chunk = [&](uint32_t stg) {
#pragma unroll
        for (int it = 0; it < 2; ++it) {
            const int slot = tid + it * 256;
            const int r    = slot >> 2;
            const int g    = slot & 3;
            const uint32_t so = sw64((uint32_t)(r * ROWB + g * 16));
            float4 u = ra[it][0], v = ra[it][1];
            sts16(stg + 0 * TILE_B + so,
                  pack_hi(u.x, u.y), pack_hi(u.z, u.w),
                  pack_hi(v.x, v.y), pack_hi(v.z, v.w));
            sts16(stg + 1 * TILE_B + so,
                  pack_lo(u.x, u.y), pack_lo(u.z, u.w),
                  pack_lo(v.x, v.y), pack_lo(v.z, v.w));
            u = rb[it][0]; v = rb[it][1];
            sts16(stg + 2 * TILE_B + so,
                  pack_hi(u.x, u.y), pack_hi(u.z, u.w),
                  pack_hi(v.x, v.y), pack_hi(v.z, v.w));
            sts16(stg + 3 * TILE_B + so,
                  pack_lo(u.x, u.y), pack_lo(u.z, u.w),
                  pack_lo(v.x, v.y), pack_lo(v.z, v.w));
        }
    };

    float acc[4][4][4];
#pragma unroll
    for (int mt = 0; mt < 4; ++mt)
#pragma unroll
        for (int nt = 0; nt < 4; ++nt)
#pragma unroll
            for (int e = 0; e < 4; ++e) acc[mt][nt][e] = 0.f;

    // Prologue: chunk 0 -> stage 0; chunk 1 in regs
    ldg_chunk(0);
    sts_chunk(base);
    ldg_chunk(BKC);
    __syncthreads();

    const uint32_t aRow = (uint32_t)(wm * 64 + (lane & 15));
    const uint32_t aCb  = (uint32_t)((lane >> 4) << 4);
    const uint32_t bRow = (uint32_t)(wn * 32 + ((lane >> 4) << 3) + (lane & 7));
    const uint32_t bCb  = (uint32_t)(((lane >> 3) & 1) << 4);

#pragma unroll 1
    for (int i = 0; i < NCHUNK; ++i) {
        const int s = i & 1;
        const uint32_t stg = base + (uint32_t)s * STAGE_B;

        // Store chunk i+1 (regs -> other stage), then start LDG of chunk i+2.
        if (i + 1 < NCHUNK) sts_chunk(base + (uint32_t)(s ^ 1) * STAGE_B);
        if (i + 2 < NCHUNK) ldg_chunk((i + 2) * BKC);

        const uint32_t sAh = stg;
        const uint32_t sAl = stg + 1 * TILE_B;
        const uint32_t sBh = stg + 2 * TILE_B;
        const uint32_t sBl = stg + 3 * TILE_B;

#pragma unroll
        for (int kk = 0; kk < 2; ++kk) {
            uint32_t bh[4][2], bl[4][2];
#pragma unroll
            for (int j = 0; j < 2; ++j) {
                const uint32_t off = sw64((bRow + j * 16) * ROWB + kk * 32 + bCb);
                uint32_t t[4];
                ldsm4(t, sBh + off);
                bh[j*2][0] = t[0]; bh[j*2][1] = t[1];
                bh[j*2+1][0] = t[2]; bh[j*2+1][1] = t[3];
                ldsm4(t, sBl + off);
                bl[j*2][0] = t[0]; bl[j*2][1] = t[1];
                bl[j*2+1][0] = t[2]; bl[j*2+1][1] = t[3];
            }
#pragma unroll
            for (int mt = 0; mt < 4; ++mt) {
                const uint32_t offA = sw64((aRow + mt * 16) * ROWB + kk * 32 + aCb);
                uint32_t ah[4];
                ldsm4(ah, sAh + offA);
#pragma unroll
                for (int nt = 0; nt < 4; ++nt) mma_bf16(acc[mt][nt], ah, bh[nt]);
#pragma unroll
                for (int nt = 0; nt < 4; ++nt) mma_bf16(acc[mt][nt], ah, bl[nt]);
                uint32_t al[4];
                ldsm4(al, sAl + offA);
#pragma unroll
                for (int nt = 0; nt < 4; ++nt) mma_bf16(acc[mt][nt], al, bh[nt]);
            }
        }
        __syncthreads();
    }

    // ---- Epilogue: bias + split to bf16 pair ----
    const int l4 = lane >> 2;
    const int l2 = (lane & 3) * 2;
#pragma unroll
    for (int mt = 0; mt < 4; ++mt) {
#pragma unroll
        for (int half = 0; half < 2; ++half) {
            const int r = rowBase + wm * 64 + mt * 16 + l4 + half * 8;
            float rbias = 0.f;
            if (BIAS_MODE == 2) rbias = __ldg(&bias[r]);
#pragma unroll
            for (int nt = 0; nt < 4; ++nt) {
                const int c = colBase + wn * 32 + nt * 8 + l2;
                float v0 = acc[mt][nt][half * 2 + 0];
                float v1 = acc[mt][nt][half * 2 + 1];
                if (BIAS_MODE == 1) {
                    float2 bv = *reinterpret_cast<const float2*>(&bias[c]);
                    v0 += bv.x; v1 += bv.y;
                } else {
                    v0 += rbias; v1 += rbias;
                }
                __nv_bfloat16 h0 = __float2bfloat16(v0);
                __nv_bfloat16 h1 = __float2bfloat16(v1);
                __nv_bfloat16 q0 = __float2bfloat16(v0 - __bfloat162float(h0));
                __nv_bfloat16 q1 = __float2bfloat16(v1 - __bfloat162float(h1));
                *reinterpret_cast<__nv_bfloat162*>(Ch + (size_t)r * ldc + c) =
                    __halves2bfloat162(h0, h1);
                *reinterpret_cast<__nv_bfloat162*>(Cl + (size_t)r * ldc + c) =
                    __halves2bfloat162(q0, q1);
            }
        }
    }
}

// ============================================================================
// gemm_split: NT GEMM on preconverted bf16 pairs (R12 proven path, unchanged)
//   OUT fp32. Used for scores and PV.
// ============================================================================
__global__ void __launch_bounds__(256, 2)
gemm_split(const __nv_bfloat16* __restrict__ Ah, const __nv_bfloat16* __restrict__ Al,
           int lda, size_t sA,
           const __nv_bfloat16* __restrict__ Bh, const __nv_bfloat16* __restrict__ Bl,
           int ldb, size_t sB,
           float* __restrict__ Cf, int ldc, size_t sC)
{
    extern __shared__ char smem[];
    const int tid  = threadIdx.x;
    const int wid  = tid >> 5;
    const int lane = tid & 31;
    const int wm   = wid >> 2;
    const int wn   = wid & 3;
    const int z    = blockIdx.z;

    Ah += (size_t)z * sA;  Al += (size_t)z * sA;
    Bh += (size_t)z * sB;  Bl += (size_t)z * sB;
    Cf += (size_t)z * sC;

    const int rowBase = blockIdx.y * 128;
    const int colBase = blockIdx.x * 128;

    const uint32_t raw  = smem_u32_of(smem);
    const uint32_t base = (raw + 1023u) & ~1023u;

    const __nv_bfloat16* aAh = Ah + (size_t)rowBase * lda;
    const __nv_bfloat16* aAl = Al + (size_t)rowBase * lda;
    const __nv_bfloat16* aBh = Bh + (size_t)colBase * ldb;
    const __nv_bfloat16* aBl = Bl + (size_t)colBase * ldb;

    auto load_chunk = [&](int k0, uint32_t stg) {
#pragma unroll
        for (int it = 0; it < 2; ++it) {
            const int slot = tid + it * 256;
            const int r    = slot >> 2;
            const int seg  = slot & 3;
            const uint32_t so = sw64((uint32_t)(r * ROWB + seg * 16));
            const size_t ga = (size_t)r * lda + k0 + seg * 8;
            const size_t gb = (size_t)r * ldb + k0 + seg * 8;
            cp16(stg + 0 * TILE_B + so, aAh + ga);
            cp16(stg + 1 * TILE_B + so, aAl + ga);
            cp16(stg + 2 * TILE_B + so, aBh + gb);
            cp16(stg + 3 * TILE_B + so, aBl + gb);
        }
        CP_COMMIT();
    };

    float acc[4][4][4];
#pragma unroll
    for (int mt = 0; mt < 4; ++mt)
#pragma unroll
        for (int nt = 0; nt < 4; ++nt)
#pragma unroll
            for (int e = 0; e < 4; ++e) acc[mt][nt][e] = 0.f;

    load_chunk(0, base + 0 * STAGE_B);
    load_chunk(BKC, base + 1 * STAGE_B);

    const uint32_t aRow = (uint32_t)(wm * 64 + (lane & 15));
    const uint32_t aCb  = (uint32_t)((lane >> 4) << 4);
    const uint32_t bRow = (uint32_t)(wn * 32 + ((lane >> 4) << 3) + (lane & 7));
    const uint32_t bCb  = (uint32_t)(((lane >> 3) & 1) << 4);

#pragma unroll 1
    for (int i = 0; i < NCHUNK; ++i) {
        if (i + 1 < NCHUNK) { CP_WAIT(1); } else { CP_WAIT(0); }
        __syncthreads();

        if (i + 2 < NCHUNK)
            load_chunk((i + 2) * BKC, base + ((i + 2) % NSTAGE) * STAGE_B);

        const uint32_t stg = base + (i % NSTAGE) * STAGE_B;
        const uint32_t sAh = stg;
        const uint32_t sAl = stg + 1 * TILE_B;
        const uint32_t sBh = stg + 2 * TILE_B;
        const uint32_t sBl = stg + 3 * TILE_B;

#pragma unroll
        for (int kk = 0; kk < 2; ++kk) {
            uint32_t bh[4][2], bl[4][2];
#pragma unroll
            for (int j = 0; j < 2; ++j) {
                const uint32_t off = sw64((bRow + j * 16) * ROWB + kk * 32 + bCb);
                uint32_t t[4];
                ldsm4(t, sBh + off);
                bh[j*2][0] = t[0]; bh[j*2][1] = t[1];
                bh[j*2+1][0] = t[2]; bh[j*2+1][1] = t[3];
                ldsm4(t, sBl + off);
                bl[j*2][0] = t[0]; bl[j*2][1] = t[1];
                bl[j*2+1][0] = t[2]; bl[j*2+1][1] = t[3];
            }
#pragma unroll
            for (int mt = 0; mt < 4; ++mt) {
                const uint32_t offA = sw64((aRow + mt * 16) * ROWB + kk * 32 + aCb);
                uint32_t ah[4];
                ldsm4(ah, sAh + offA);
#pragma unroll
                for (int nt = 0; nt < 4; ++nt) mma_bf16(acc[mt][nt], ah, bh[nt]);
#pragma unroll
                for (int nt = 0; nt < 4; ++nt) mma_bf16(acc[mt][nt], ah, bl[nt]);
                uint32_t al[4];
                ldsm4(al, sAl + offA);
#pragma unroll
                for (int nt = 0; nt < 4; ++nt) mma_bf16(acc[mt][nt], al, bh[nt]);
            }
        }
    }

    const int l4 = lane >> 2;
    const int l2 = (lane & 3) * 2;
#pragma unroll
    for (int mt = 0; mt < 4; ++mt) {
#pragma unroll
        for (int half = 0; half < 2; ++half) {
            const int r = rowBase + wm * 64 + mt * 16 + l4 + half * 8;
#pragma unroll
            for (int nt = 0; nt < 4; ++nt) {
                const int c = colBase + wn * 32 + nt * 8 + l2;
                float2 st;
                st.x = acc[mt][nt][half * 2 + 0];
                st.y = acc[mt][nt][half * 2 + 1];
                *reinterpret_cast<float2*>(Cf + (size_t)r * ldc + c) = st;
            }
        }
    }
}

// ============================================================================
// Row softmax over 1024-wide rows; fp32 in, bf16 hi/lo split out.
// ============================================================================
__global__ void __launch_bounds__(256)
softmax_split(const float* __restrict__ S, __nv_bfloat16* __restrict__ Ph,
              __nv_bfloat16* __restrict__ Pl)
{
    const int row = blockIdx.x;
    const int t = threadIdx.x;
    const int w = t >> 5, l = t & 31;

    float4 v = *reinterpret_cast<const float4*>(S + (size_t)row * 1024 + t * 4);

    float m = fmaxf(fmaxf(v.x, v.y), fmaxf(v.z, v.w));
#pragma unroll
    for (int o = 16; o; o >>= 1) m = fmaxf(m, __shfl_xor_sync(0xffffffffu, m, o));

    __shared__ float redm[8], reds[8];
    if (l == 0) redm[w] = m;
    __syncthreads();
    float rm = fmaxf(fmaxf(fmaxf(redm[0], redm[1]), fmaxf(redm[2], redm[3])),
                     fmaxf(fmaxf(redm[4], redm[5]), fmaxf(redm[6], redm[7])));

    v.x = __expf(v.x - rm);
    v.y = __expf(v.y - rm);
    v.z = __expf(v.z - rm);
    v.w = __expf(v.w - rm);

    float s = v.x + v.y + v.z + v.w;
#pragma unroll
    for (int o = 16; o; o >>= 1) s += __shfl_xor_sync(0xffffffffu, s, o);
    if (l == 0) reds[w] = s;
    __syncthreads();
    float tot = (reds[0] + reds[1]) + (reds[2] + reds[3])
              + (reds[4] + reds[5]) + (reds[6] + reds[7]);

    const float inv = 1.0f / tot;
    float w0 = v.x * inv, w1 = v.y * inv, w2 = v.z * inv, w3 = v.w * inv;

    __nv_bfloat16 h0 = __float2bfloat16(w0), h1 = __float2bfloat16(w1);
    __nv_bfloat16 h2 = __float2bfloat16(w2), h3 = __float2bfloat16(w3);
    __nv_bfloat16 l0 = __float2bfloat16(w0 - __bfloat162float(h0));
    __nv_bfloat16 l1 = __float2bfloat16(w1 - __bfloat162float(h1));
    __nv_bfloat16 l2 = __float2bfloat16(w2 - __bfloat162float(h2));
    __nv_bfloat16 l3 = __float2bfloat16(w3 - __bfloat162float(h3));

    const size_t p2 = ((size_t)row * 1024 + t * 4) >> 1;
    reinterpret_cast<__nv_bfloat162*>(Ph)[p2 + 0] = __halves2bfloat162(h0, h1);
    reinterpret_cast<__nv_bfloat162*>(Ph)[p2 + 1] = __halves2bfloat162(h2, h3);
    reinterpret_cast<__nv_bfloat162*>(Pl)[p2 + 0] = __halves2bfloat162(l0, l1);
    reinterpret_cast<__nv_bfloat162*>(Pl)[p2 + 1] = __halves2bfloat162(l2, l3);
}

// ============================================================================
// kernel_launch — 3-stream Q/K/V dependency graph, splits fused into GEMMs:
//   main: Q-proj(conv) -> [wait K] scores -> softmax -> [wait V] PV
//   s1:   K-proj(conv)
//   s2:   VT-proj(conv)   (overlaps scores+softmax)
// ============================================================================
extern "C" void kernel_launch(void* const* d_in, const int* in_sizes, int n_in,
                              void* d_out, int out_size)
{
    const float* meme  = (const float*)d_in[0];
    const float* text  = (const float*)d_in[1];
    const float* emoji = (const float*)d_in[2];
    const float* Wq    = (const float*)d_in[3];
    const float* bq    = (const float*)d_in[4];
    const float* Wk    = (const float*)d_in[5];
    const float* bk    = (const float*)d_in[6];
    const float* Wv    = (const float*)d_in[7];
    const float* bv    = (const float*)d_in[8];
    float* out = (float*)d_out;

    __nv_bfloat16 *Qh,*Ql,*Kh,*Kl,*VTh,*VTl,*Ph,*Pl;
    float* S;
    cudaGetSymbolAddress((void**)&Qh, g_Qh);   cudaGetSymbolAddress((void**)&Ql, g_Ql);
    cudaGetSymbolAddress((void**)&Kh, g_Kh);   cudaGetSymbolAddress((void**)&Kl, g_Kl);
    cudaGetSymbolAddress((void**)&VTh, g_VTh); cudaGetSymbolAddress((void**)&VTl, g_VTl);
    cudaGetSymbolAddress((void**)&Ph, g_Ph);   cudaGetSymbolAddress((void**)&Pl, g_Pl);
    cudaGetSymbolAddress((void**)&S, g_S);

    static bool inited = false;
    static cudaStream_t s1, s2;
    static cudaEvent_t evFork, evK, evV;
    if (!inited) {
        cudaStreamCreateWithFlags(&s1, cudaStreamNonBlocking);
        cudaStreamCreateWithFlags(&s2, cudaStreamNonBlocking);
        cudaEventCreateWithFlags(&evFork, cudaEventDisableTiming);
        cudaEventCreateWithFlags(&evK, cudaEventDisableTiming);
        cudaEventCreateWithFlags(&evV, cudaEventDisableTiming);
        cudaFuncSetAttribute(gemm_conv<1>, cudaFuncAttributeMaxDynamicSharedMemorySize, CONV_SMEM);
        cudaFuncSetAttribute(gemm_conv<2>, cudaFuncAttributeMaxDynamicSharedMemorySize, CONV_SMEM);
        cudaFuncSetAttribute(gemm_split, cudaFuncAttributeMaxDynamicSharedMemorySize, GEMM_SMEM);
        inited = true;
    }

    const size_t bstr = (size_t)SEQ * HID;          // 1M elems per batch
    dim3 blk(256);
    dim3 gProj(HID / 128, MTOT / 128, 1);           // (8, 128)
    dim3 gVT(MTOT / 128, HID / 128, 1);             // (128, 8)
    dim3 gAtt(SEQ / 128, SEQ / 128, NBAT);          // (8, 8, 16)

    // Fork side streams from the capture-origin stream.
    cudaEventRecord(evFork, 0);
    cudaStreamWaitEvent(s1, evFork, 0);
    cudaStreamWaitEvent(s2, evFork, 0);

    // s1: K path — K[l][a] = text[l][:] . Wk[a][:] + bk[a]
    gemm_conv<1><<<gProj, blk, CONV_SMEM, s1>>>(text, HID, Wk, HID, bk, Kh, Kl, HID);
    cudaEventRecord(evK, s1);

    // s2: V path — VT[a][lg] = Wv[a][:] . emoji[lg][:] + bv[a]   (ldc = 16384)
    gemm_conv<2><<<gVT, blk, CONV_SMEM, s2>>>(Wv, HID, emoji, HID, bv, VTh, VTl, MTOT);
    cudaEventRecord(evV, s2);

    // main: Q path — Q[l][a] = meme[l][:] . Wq[a][:] + bq[a]
    gemm_conv<1><<<gProj, blk, CONV_SMEM>>>(meme, HID, Wq, HID, bq, Qh, Ql, HID);

    // Need K before scores (VT overlaps scores+softmax).
    cudaStreamWaitEvent(0, evK, 0);
    gemm_split<<<gAtt, blk, GEMM_SMEM>>>(Qh, Ql, HID, bstr, Kh, Kl, HID, bstr,
                                         S, SEQ, bstr);
    softmax_split<<<MTOT, blk>>>(S, Ph, Pl);

    // Need VT before PV.
    cudaStreamWaitEvent(0, evV, 0);
    gemm_split<<<gAtt, blk, GEMM_SMEM>>>(Ph, Pl, SEQ, bstr,
                                         VTh, VTl, MTOT, (size_t)SEQ,
                                         out, HID, bstr);
}